// round 17
// baseline (speedup 1.0000x reference)
#include <cuda_runtime.h>
#include <cstdint>

#define IN_CHAN 4096
#define BATCH   16
#define NTOT    (3 * IN_CHAN)          // 12288 stacked W rows (q,k,v)
#define KSPLIT  16
#define KS_LEN  (IN_CHAN / KSPLIT)     // 256 k per block
#define ROWS_PB 64                     // W rows per block (4 warps x 16)
#define NNODES  32
#define NCHUNK  16
#define CHLEN   (IN_CHAN / NCHUNK)     // 256
#define QHALF   4.0f
#define LOG2E   1.4426950408889634f
#define PI_F    3.14159265358979323846f

#define XW      132                    // x smem row pitch in b32 words (even)

// Scratch (device globals; no allocation allowed anywhere)
__device__ float g_part[KSPLIT * NTOT * BATCH];       // split-K partials (12.6MB)
__device__ float g_qkv[3 * BATCH * IN_CHAN];          // reduced q,k,v (b-major)
__device__ float g_nodes[BATCH][NCHUNK][2][NNODES];   // per j-chunk partial F,G
__device__ unsigned int g_cnt[BATCH];                 // producer counters

__device__ __forceinline__ float ex2(float x) {
    float r;
    asm("ex2.approx.ftz.f32 %0, %1;" : "=f"(r) : "f"(x));
    return r;
}
__device__ __forceinline__ uint32_t packbf(float hi_elem, float lo_elem) {
    uint32_t r;
    asm("cvt.rn.bf16x2.f32 %0, %1, %2;" : "=r"(r) : "f"(hi_elem), "f"(lo_elem));
    return r;
}
// split adjacent pair (lo=a, hi=b) into bf16x2 hi and lo parts
__device__ __forceinline__ void split2(float a, float b, uint32_t& hi, uint32_t& lo) {
    hi = packbf(b, a);
    float ah = __uint_as_float(hi << 16);
    float bh = __uint_as_float(hi & 0xffff0000u);
    lo = packbf(b - bh, a - ah);
}
// m16n8k16 bf16 MMA, fp32 accumulate
__device__ __forceinline__ void mma16816(float* d, const uint32_t* a,
                                         uint32_t b0, uint32_t b1) {
    asm volatile(
        "mma.sync.aligned.m16n8k16.row.col.f32.bf16.bf16.f32 "
        "{%0,%1,%2,%3}, {%4,%5,%6,%7}, {%8,%9}, {%0,%1,%2,%3};"
        : "+f"(d[0]), "+f"(d[1]), "+f"(d[2]), "+f"(d[3])
        : "r"(a[0]), "r"(a[1]), "r"(a[2]), "r"(a[3]), "r"(b0), "r"(b1));
}

// ---------------------------------------------------------------------------
// Kernel 1: QKV GEMM on tensor cores (bf16x3 split), split-K, wave-balanced,
// k-permuted fragments, prefetch depth 2 (unchanged from R16).
// ---------------------------------------------------------------------------
__global__ __launch_bounds__(128, 7) void qkv_gemm_kernel(
    const float* __restrict__ x,
    const float* __restrict__ wq,
    const float* __restrict__ wk,
    const float* __restrict__ wv)
{
    __shared__ __align__(16) uint32_t xhi[BATCH * XW];   // [n][k/2] bf16 pairs
    __shared__ __align__(16) uint32_t xlo[BATCH * XW];

    const int tid  = threadIdx.x;
    const int wid  = tid >> 5;
    const int lane = tid & 31;

    const int gn0 = blockIdx.x * ROWS_PB;
    const int mat = gn0 >> 12;
    const int n0  = gn0 & (IN_CHAN - 1);
    const int kb  = blockIdx.y * KS_LEN;
    const float* w = (mat == 0) ? wq : (mat == 1) ? wk : wv;

    // ---- stage x slice as bf16 hi/lo: 16 b x (KS_LEN/2=128) float2 ----
#pragma unroll
    for (int i = 0; i < 16; ++i) {
        int idx = tid + i * 128;        // [0,2048)
        int b   = idx >> 7;
        int kw  = idx & 127;
        float2 f = *(const float2*)(x + (size_t)b * IN_CHAN + kb + kw * 2);
        uint32_t h, l;
        split2(f.x, f.y, h, l);
        xhi[b * XW + kw] = h;
        xlo[b * XW + kw] = l;
    }
    __syncthreads();

    const int m0  = n0 + wid * 16;      // warp's m-tile base row
    const int la4 = lane >> 2;
    const int t4  = (lane & 3) * 4;     // A col base (k-permuted)
    const int c0  = (lane & 3) * 2;     // D col base (output)

    const float* p0 = w + (size_t)(m0 + la4)     * IN_CHAN + kb + t4;
    const float* p1 = w + (size_t)(m0 + la4 + 8) * IN_CHAN + kb + t4;

    float d[2][4];                      // [n-tile][frag]
#pragma unroll
    for (int n = 0; n < 2; ++n)
#pragma unroll
        for (int j = 0; j < 4; ++j) d[n][j] = 0.f;

    const int brow0 = la4 * XW;         // n-tile 0 row base
    const int brow1 = (8 + la4) * XW;   // n-tile 1

    // prefetch depth 2
    float4 pfA0 = *(const float4*)p0;
    float4 pfA1 = *(const float4*)p1;
    float4 pfB0 = *(const float4*)(p0 + 16);
    float4 pfB1 = *(const float4*)(p1 + 16);

#pragma unroll 4
    for (int k = 0; k < KS_LEN; k += 16) {
        float4 cur0 = pfA0, cur1 = pfA1;
        pfA0 = pfB0;
        pfA1 = pfB1;
        if (k + 32 < KS_LEN) {
            pfB0 = *(const float4*)(p0 + k + 32);
            pfB1 = *(const float4*)(p1 + k + 32);
        }

        uint32_t ah[4], al[4];
        split2(cur0.x, cur0.y, ah[0], al[0]);
        split2(cur1.x, cur1.y, ah[1], al[1]);
        split2(cur0.z, cur0.w, ah[2], al[2]);
        split2(cur1.z, cur1.w, ah[3], al[3]);

        const int kw = (k >> 1) + c0;           // even -> 8B aligned
        uint2 bh0 = *(const uint2*)&xhi[brow0 + kw];
        uint2 bl0 = *(const uint2*)&xlo[brow0 + kw];
        uint2 bh1 = *(const uint2*)&xhi[brow1 + kw];
        uint2 bl1 = *(const uint2*)&xlo[brow1 + kw];

        mma16816(d[0], ah, bh0.x, bh0.y);       // hi*hi
        mma16816(d[0], ah, bl0.x, bl0.y);       // hi*lo
        mma16816(d[0], al, bh0.x, bh0.y);       // lo*hi
        mma16816(d[1], ah, bh1.x, bh1.y);
        mma16816(d[1], ah, bl1.x, bl1.y);
        mma16816(d[1], al, bh1.x, bh1.y);
    }

    const int p = blockIdx.y;
#pragma unroll
    for (int n = 0; n < 2; ++n) {
        int gnA  = gn0 + wid * 16 + la4;
        int bcol = n * 8 + c0;
        float* dstA = g_part + ((size_t)p * NTOT + gnA) * BATCH + bcol;
        *(float2*)dstA = make_float2(d[n][0], d[n][1]);
        float* dstB = g_part + ((size_t)p * NTOT + gnA + 8) * BATCH + bcol;
        *(float2*)dstB = make_float2(d[n][2], d[n][3]);
    }
}

// ---------------------------------------------------------------------------
// Kernel 2: coalesced split-K reduce + bias -> g_qkv (b-major).
// Also re-zeroes g_cnt for the fused tail (graph replay safe: this kernel
// always precedes the tail in stream order).
// ---------------------------------------------------------------------------
__global__ __launch_bounds__(256) void reduce_bias_kernel(
    const float* __restrict__ bq,
    const float* __restrict__ bk,
    const float* __restrict__ bv)
{
    if (blockIdx.x == 0 && threadIdx.x < BATCH)
        g_cnt[threadIdx.x] = 0u;

    const int idx = blockIdx.x * 256 + threadIdx.x;   // [0, NTOT*BATCH)
    const int b   = idx & (BATCH - 1);
    const int gn  = idx >> 4;
    const int mat = gn >> 12;
    const int n   = gn & (IN_CHAN - 1);

    float s = 0.f;
#pragma unroll
    for (int p = 0; p < KSPLIT; ++p)
        s += g_part[(size_t)p * NTOT * BATCH + idx];

    const float* bias = (mat == 0) ? bq : (mat == 1) ? bk : bv;
    g_qkv[((size_t)mat * BATCH + b) * IN_CHAN + n] = s + bias[n];
}

// ---------------------------------------------------------------------------
// Kernel 3: FUSED tail (nodes + fit + eval in ONE launch).
// grid = 272 blocks x 512 thr, all co-resident (<=592 slots) -> the
// producer/consumer spin is deadlock-free and deterministic.
//   blocks [0,256): nodes producer for (b = bid&15, ch = bid>>4); writes
//     g_nodes[b][ch], threadfence, bumps g_cnt[b].
//   blocks [256,272): consumer for batch b = bid-256; spins until
//     g_cnt[b]==NCHUNK, then chunk-sum + 32x32 DCT (__cosf) + Clenshaw for
//     all 4096 outputs of the batch (8 per thread).
// ---------------------------------------------------------------------------
__global__ __launch_bounds__(512) void attn_tail_kernel(float* __restrict__ out)
{
    const int bid = blockIdx.x;
    const int tid = threadIdx.x;

    if (bid < BATCH * NCHUNK) {
        // ---------------- producer: node partials for one (b, ch) chunk ----
        __shared__ float ks[CHLEN], vs[CHLEN];
        const int b  = bid & (BATCH - 1);
        const int ch = bid >> 4;

        {
            int n   = tid & (CHLEN - 1);
            int sel = tid >> 8;         // 0 = k (mat 1), 1 = v (mat 2)
            float s = g_qkv[((size_t)(1 + sel) * BATCH + b) * IN_CHAN + ch * CHLEN + n];
            if (sel) vs[n] = s;
            else     ks[n] = s;
        }
        __syncthreads();

        const int node = tid >> 4;
        const int sub  = tid & 15;

        const float xt = QHALF * __cosf(PI_F * (node + 0.5f) / NNODES);
        const float a  = xt * LOG2E;

        float aF = 0.f, aG = 0.f;
#pragma unroll
        for (int j = sub; j < CHLEN; j += 16) {
            float e = ex2(a * ks[j]);
            aG += e;
            aF = fmaf(e, vs[j], aF);
        }
#pragma unroll
        for (int o = 8; o; o >>= 1) {
            aF += __shfl_xor_sync(0xffffffffu, aF, o);
            aG += __shfl_xor_sync(0xffffffffu, aG, o);
        }
        if (sub == 0) {
            g_nodes[b][ch][0][node] = aF;
            g_nodes[b][ch][1][node] = aG;
        }
        __syncthreads();
        __threadfence();                // publish g_nodes before counting
        if (tid == 0)
            atomicAdd(&g_cnt[b], 1u);
    } else {
        // ---------------- consumer: fit + eval for one batch ---------------
        __shared__ float Fv[NNODES], Gv[NNODES], cF[NNODES], cG[NNODES];
        const int b = bid - BATCH * NCHUNK;

        if (tid == 0) {
            while (atomicAdd(&g_cnt[b], 0u) < (unsigned)NCHUNK) { }
        }
        __syncthreads();
        __threadfence();                // acquire g_nodes writes

        if (tid < 64) {
            int node = tid & 31;
            int sel  = tid >> 5;
            float v = 0.f;
#pragma unroll
            for (int ch = 0; ch < NCHUNK; ++ch)
                v += g_nodes[b][ch][sel][node];
            if (sel == 0) Fv[node] = v;
            else          Gv[node] = v;
        }
        __syncthreads();

        if (tid < 64) {
            int m = tid & 31;
            const float* src = (tid < 32) ? Fv : Gv;
            float c = 0.f;
#pragma unroll
            for (int t = 0; t < NNODES; ++t) {
                int u = (m * (2 * t + 1)) & 127;
                c = fmaf(src[t], __cosf((PI_F / 64.0f) * (float)u), c);
            }
            c *= 2.0f / NNODES;
            if (tid < 32) cF[m] = c;
            else          cG[m] = c;
        }
        __syncthreads();

#pragma unroll
        for (int r = 0; r < IN_CHAN / 512; ++r) {
            const int i = r * 512 + tid;
            float q = g_qkv[(size_t)b * IN_CHAN + i];   // mat 0 = q

            float y = q * (1.0f / QHALF);
            y = fminf(1.f, fmaxf(-1.f, y));
            const float y2 = 2.f * y;

            float f1 = 0.f, f2 = 0.f, g1 = 0.f, g2 = 0.f;
#pragma unroll
            for (int m = NNODES - 1; m >= 1; --m) {
                float tf = fmaf(y2, f1, cF[m] - f2);
                f2 = f1; f1 = tf;
                float tg = fmaf(y2, g1, cG[m] - g2);
                g2 = g1; g1 = tg;
            }
            float F = fmaf(y, f1, 0.5f * cF[0]) - f2;
            float G = fmaf(y, g1, 0.5f * cG[0]) - g2;

            out[(size_t)b * IN_CHAN + i] = F / G;
        }
    }
}

// ---------------------------------------------------------------------------
extern "C" void kernel_launch(void* const* d_in, const int* in_sizes, int n_in,
                              void* d_out, int out_size)
{
    (void)in_sizes; (void)n_in; (void)out_size;
    const float* x  = (const float*)d_in[0];
    const float* wq = (const float*)d_in[1];
    const float* bq = (const float*)d_in[2];
    const float* wk = (const float*)d_in[3];
    const float* bk = (const float*)d_in[4];
    const float* wv = (const float*)d_in[5];
    const float* bv = (const float*)d_in[6];
    float* out = (float*)d_out;

    qkv_gemm_kernel<<<dim3(NTOT / ROWS_PB, KSPLIT), 128>>>(x, wq, wk, wv);
    reduce_bias_kernel<<<(NTOT * BATCH) / 256, 256>>>(bq, bk, bv);
    attn_tail_kernel<<<BATCH * NCHUNK + BATCH, 512>>>(out);
}